// round 9
// baseline (speedup 1.0000x reference)
#include <cuda_runtime.h>
#include <cooperative_groups.h>

namespace cg = cooperative_groups;

#define BATCH   64
#define NGT     1024
#define MPRED   2048
#define THRESH2 256.0f    // 16.0^2
#define GDIM    32        // 32x32 grid of 16px cells (512 / 16)
#define NCELL   (GDIM * GDIM)

// Cluster of 2 CTAs (1024 threads) per batch; grid = 128. Each CTA bins the
// batch's 1024 gts into a 32x32 cell CSR in its own smem, then scans 1024
// preds (rank r -> preds [r*1024, ...)) against the 3x3 cell neighborhood —
// exactly equivalent to the full argmin (matches only matter under the 16px
// threshold; any gt within 16px lies in the 3x3 neighborhood). Both ranks
// atomicMin (gt -> min pred index) into RANK 0's s_best (DSMEM for rank 1).
//
// Tail sync is a ONE-WAY handoff instead of cluster.sync() (which blocks
// ~380-490cyc and flushes L1D via CCTL.IVALL right before the gather's
// scattered loads): rank1 publishes via bar.sync -> tid0
// fence.acq_rel.cluster -> mbarrier arrive (release.cluster) and exits;
// rank0 tid0 waits + fences, then __syncthreads propagates the acquire to
// all reader threads (transitive happens-before). mbarrier init ordering is
// covered by a SPLIT cluster barrier: arrive right after init (non-blocking),
// wait deferred to just before use (complete by then, ~0 cost).
//
// d2 uses __fadd_rn/__fmul_rn (no FMA) -> bit-identical to the reference;
// tie rule (equal d2 -> lower gt index) explicit -> order-invariant.
__global__ __launch_bounds__(1024, 1) __cluster_dims__(2, 1, 1)
void lacss_match_kernel(
    const float2* __restrict__ gt,    // [BATCH, NGT]
    const float2* __restrict__ pred,  // [BATCH, MPRED]
    float2* __restrict__ out)         // [BATCH, NGT]
{
    __shared__ int    s_cnt[NCELL];      // counts, then scatter cursor
    __shared__ int    s_off[NCELL + 1];  // exclusive CSR offsets
    __shared__ float4 s_pt[NGT];         // {gx, gy, idx-as-float, pad} binned
    __shared__ int    s_best[NGT];       // min matched pred j per gt (rank0 authoritative)
    __shared__ int    s_wsum[32];
    __shared__ __align__(8) unsigned long long s_mbar;  // rank0's completion barrier

    cg::cluster_group cluster = cg::this_cluster();
    const unsigned rank = cluster.block_rank();

    const int b    = blockIdx.x >> 1;
    const int tid  = threadIdx.x;
    const int lane = tid & 31;
    const int wid  = tid >> 5;

    // smem address of s_mbar (for mbarrier PTX)
    uint32_t mbar_addr;
    asm("{ .reg .u64 t; cvta.to.shared.u64 t, %1; cvt.u32.u64 %0, t; }"
        : "=r"(mbar_addr) : "l"(&s_mbar));

    // ---- prefetch both inputs (MLP=2, DRAM latency behind binning) ----
    const int j = (int)rank * 1024 + tid;          // this thread's pred
    const float2 p = pred[b * MPRED + j];
    const float2 g = gt[b * NGT + tid];

    if (rank == 0 && tid == 0) {
        asm volatile("mbarrier.init.shared.b64 [%0], 1;" :: "r"(mbar_addr) : "memory");
    }
    s_cnt[tid]  = 0;
    s_best[tid] = MPRED;                 // sentinel: unmatched
    __syncthreads();
    // Split cluster barrier: arrive now (publishes mbarrier init, release
    // at cluster scope, non-blocking); wait deferred to just before use.
    asm volatile("barrier.cluster.arrive.aligned;" ::: "memory");

    // ---- count (cell = y/16 * 32 + x/16; *2^-4 exact) ----
    const int gcell = (int)(g.y * 0.0625f) * GDIM + (int)(g.x * 0.0625f);
    atomicAdd(&s_cnt[gcell], 1);
    __syncthreads();

    // ---- exclusive prefix sum of s_cnt -> s_off ----
    int v   = s_cnt[tid];
    int inc = v;
    #pragma unroll
    for (int d = 1; d < 32; d <<= 1) {
        int n = __shfl_up_sync(0xFFFFFFFFu, inc, d);
        if (lane >= d) inc += n;
    }
    if (lane == 31) s_wsum[wid] = inc;
    __syncthreads();
    if (wid == 0) {
        int w  = s_wsum[lane];
        int wi = w;
        #pragma unroll
        for (int d = 1; d < 32; d <<= 1) {
            int n = __shfl_up_sync(0xFFFFFFFFu, wi, d);
            if (lane >= d) wi += n;
        }
        s_wsum[lane] = wi - w;           // exclusive offset of warp `lane`
    }
    __syncthreads();
    const int excl = (inc - v) + s_wsum[wid];
    s_off[tid] = excl;
    if (tid == 0) s_off[NCELL] = NGT;
    s_cnt[tid] = excl;                   // cursor = copy of offsets
    __syncthreads();

    // ---- scatter gts into binned order, original idx packed into .z ----
    {
        int pos = atomicAdd(&s_cnt[gcell], 1);
        s_pt[pos] = make_float4(g.x, g.y, __int_as_float(tid), 0.f);
    }
    __syncthreads();

    // ---- pred phase: one pred per thread, 3x3 neighborhood (3 runs) ----
    {
        const int pcx = (int)(p.x * 0.0625f);
        const int pcy = (int)(p.y * 0.0625f);
        const int x0 = max(pcx - 1, 0), x1 = min(pcx + 1, GDIM - 1);
        const int y0 = max(pcy - 1, 0), y1 = min(pcy + 1, GDIM - 1);

        float best = THRESH2;            // strict < doubles as threshold test
        int   bi   = -1;

        for (int cy = y0; cy <= y1; cy++) {
            const int ks = s_off[cy * GDIM + x0];
            const int ke = s_off[cy * GDIM + x1 + 1];   // cells contiguous in x
            for (int k = ks; k < ke; k++) {
                float4 q = s_pt[k];                     // one LDS.128
                int   gi = __float_as_int(q.z);
                float dx = __fadd_rn(p.x, -q.x);
                float dy = __fadd_rn(p.y, -q.y);
                float d2 = __fadd_rn(__fmul_rn(dx, dx), __fmul_rn(dy, dy));
                bool take = (d2 < best) || (d2 == best && gi < bi);
                bi   = take ? gi : bi;
                best = take ? d2 : best;
            }
        }

        if (bi >= 0) {
            int* dst = (rank == 0) ? s_best
                                   : cluster.map_shared_rank(s_best, 0);
            atomicMin(&dst[bi], j);
        }
    }

    // Complete the early split barrier (long since arrived by all -> ~free).
    asm volatile("barrier.cluster.wait.aligned;" ::: "memory");

    if (rank == 1) {
        // publish: all rank1 atomics -> cta bar -> tid0 cluster fence ->
        // release-arrive on rank0's mbarrier. Then exit.
        __syncthreads();
        if (tid == 0) {
            asm volatile("fence.acq_rel.cluster;" ::: "memory");
            asm volatile(
                "{\n\t"
                ".reg .b32 remAddr;\n\t"
                "mapa.shared::cluster.u32 remAddr, %0, 0;\n\t"
                "mbarrier.arrive.release.cluster.shared::cluster.b64 _, [remAddr];\n\t"
                "}"
                :: "r"(mbar_addr) : "memory");
        }
        return;
    }

    // rank 0: tid0 waits for rank1's arrive (+ cluster acquire), then a cta
    // barrier propagates the acquired state to all threads (and orders
    // rank0's own local atomics).
    if (tid == 0) {
        unsigned done;
        asm volatile(
            "{\n\t"
            ".reg .pred P;\n\t"
            "WAIT_%=:\n\t"
            "mbarrier.try_wait.parity.acquire.cluster.shared::cta.b64 P, [%1], 0, 0x989680;\n\t"
            "selp.b32 %0, 1, 0, P;\n\t"
            "@P bra DONE_%=;\n\t"
            "bra WAIT_%=;\n\t"
            "DONE_%=:\n\t"
            "}"
            : "=r"(done) : "r"(mbar_addr) : "memory");
        asm volatile("fence.acq_rel.cluster;" ::: "memory");
    }
    __syncthreads();

    // ---- fused gather by rank 0 ----
    {
        const int s = s_best[tid];
        out[b * NGT + tid] = (s < MPRED) ? pred[b * MPRED + s] : g;
    }
}

extern "C" void kernel_launch(void* const* d_in, const int* in_sizes, int n_in,
                              void* d_out, int out_size) {
    const float2* gt   = (const float2*)d_in[0];   // gt_locations   [64,1024,2] f32
    const float2* pred = (const float2*)d_in[1];   // pred_locations [64,2048,2] f32
    float2* out = (float2*)d_out;                  // [64,1024,2] f32

    lacss_match_kernel<<<BATCH * 2, 1024>>>(gt, pred, out);
}

// round 10
// speedup vs baseline: 1.1130x; 1.1130x over previous
#include <cuda_runtime.h>
#include <cooperative_groups.h>

namespace cg = cooperative_groups;

#define BATCH   64
#define NGT     1024
#define MPRED   2048
#define THRESH2 256.0f    // 16.0^2
#define GDIM    32        // 32x32 grid of 16px cells (512 / 16)
#define NCELL   (GDIM * GDIM)

// Cluster of 2 CTAs (1024 threads) per batch; grid = 128. Each CTA bins the
// batch's 1024 gts into a 32x32 cell CSR in its own smem, then scans 1024
// preds (rank r -> preds [r*1024, ...)) against the 3x3 cell neighborhood —
// exactly equivalent to the full argmin (matches only matter under the 16px
// threshold, and any gt within 16px of a pred lies in the 3x3 neighborhood
// of the pred's cell). Both ranks atomicMin (gt -> min pred index) into
// RANK 0's s_best (DSMEM atomic for rank 1); cluster.sync() orders them;
// rank 0 does the fused gather.
//
// New in R10: the full 2048-pred slab is staged into rank0's s_pred at kernel
// entry (rank0 local STS, rank1 one fire-and-forget DSMEM STS per thread,
// fully overlapped with binning; ordered before the gather by the existing
// cluster.sync). The tail gather becomes pure 29-cyc LDS instead of
// scattered LDG with ~50% L2-latency hits. Disjoint index ranges per rank,
// no reads before cluster.sync -> race-free.
//
// d2 uses __fadd_rn/__fmul_rn (no FMA) -> bit-identical to the reference;
// tie rule (equal d2 -> lower gt index) explicit -> order-invariant.
__global__ __launch_bounds__(1024, 1) __cluster_dims__(2, 1, 1)
void lacss_match_kernel(
    const float2* __restrict__ gt,    // [BATCH, NGT]
    const float2* __restrict__ pred,  // [BATCH, MPRED]
    float2* __restrict__ out)         // [BATCH, NGT]
{
    __shared__ int    s_cnt[NCELL];      // counts, then scatter cursor
    __shared__ int    s_off[NCELL + 1];  // exclusive CSR offsets
    __shared__ float4 s_pt[NGT];         // {gx, gy, idx-as-float, pad} binned
    __shared__ int    s_best[NGT];       // min matched pred j per gt (rank0 authoritative)
    __shared__ float2 s_pred[MPRED];     // full pred slab (rank0 authoritative)
    __shared__ int    s_wsum[32];

    cg::cluster_group cluster = cg::this_cluster();
    const unsigned rank = cluster.block_rank();

    const int b    = blockIdx.x >> 1;
    const int tid  = threadIdx.x;
    const int lane = tid & 31;
    const int wid  = tid >> 5;

    // ---- prefetch both inputs (MLP=2, DRAM latency behind binning) ----
    const int j = (int)rank * 1024 + tid;          // this thread's pred
    const float2 p = pred[b * MPRED + j];
    const float2 g = gt[b * NGT + tid];

    s_cnt[tid]  = 0;
    s_best[tid] = MPRED;                 // sentinel: unmatched
    __syncthreads();

    // ---- stage pred slab into rank0's smem (overlapped with binning;
    //      visibility at the tail via cluster.sync) ----
    {
        float2* dst = (rank == 0) ? s_pred
                                  : cluster.map_shared_rank(s_pred, 0);
        dst[j] = p;                      // disjoint ranges per rank
    }

    // ---- count (cell = y/16 * 32 + x/16; *2^-4 exact) ----
    const int gcell = (int)(g.y * 0.0625f) * GDIM + (int)(g.x * 0.0625f);
    atomicAdd(&s_cnt[gcell], 1);
    __syncthreads();

    // ---- exclusive prefix sum of s_cnt -> s_off ----
    int v   = s_cnt[tid];
    int inc = v;
    #pragma unroll
    for (int d = 1; d < 32; d <<= 1) {
        int n = __shfl_up_sync(0xFFFFFFFFu, inc, d);
        if (lane >= d) inc += n;
    }
    if (lane == 31) s_wsum[wid] = inc;
    __syncthreads();
    if (wid == 0) {
        int w  = s_wsum[lane];
        int wi = w;
        #pragma unroll
        for (int d = 1; d < 32; d <<= 1) {
            int n = __shfl_up_sync(0xFFFFFFFFu, wi, d);
            if (lane >= d) wi += n;
        }
        s_wsum[lane] = wi - w;           // exclusive offset of warp `lane`
    }
    __syncthreads();
    const int excl = (inc - v) + s_wsum[wid];
    s_off[tid] = excl;
    if (tid == 0) s_off[NCELL] = NGT;
    s_cnt[tid] = excl;                   // cursor = copy of offsets
    __syncthreads();

    // ---- scatter gts into binned order, original idx packed into .z ----
    {
        int pos = atomicAdd(&s_cnt[gcell], 1);
        s_pt[pos] = make_float4(g.x, g.y, __int_as_float(tid), 0.f);
    }
    __syncthreads();

    // ---- pred phase: one pred per thread, 3x3 neighborhood (3 runs) ----
    {
        const int pcx = (int)(p.x * 0.0625f);
        const int pcy = (int)(p.y * 0.0625f);
        const int x0 = max(pcx - 1, 0), x1 = min(pcx + 1, GDIM - 1);
        const int y0 = max(pcy - 1, 0), y1 = min(pcy + 1, GDIM - 1);

        float best = THRESH2;            // strict < doubles as threshold test
        int   bi   = -1;

        for (int cy = y0; cy <= y1; cy++) {
            const int ks = s_off[cy * GDIM + x0];
            const int ke = s_off[cy * GDIM + x1 + 1];   // cells contiguous in x
            for (int k = ks; k < ke; k++) {
                float4 q = s_pt[k];                     // one LDS.128
                int   gi = __float_as_int(q.z);
                float dx = __fadd_rn(p.x, -q.x);
                float dy = __fadd_rn(p.y, -q.y);
                float d2 = __fadd_rn(__fmul_rn(dx, dx), __fmul_rn(dy, dy));
                bool take = (d2 < best) || (d2 == best && gi < bi);
                bi   = take ? gi : bi;
                best = take ? d2 : best;
            }
        }

        if (bi >= 0) {
            int* dst = (rank == 0) ? s_best
                                   : cluster.map_shared_rank(s_best, 0);
            atomicMin(&dst[bi], j);
        }
    }

    cluster.sync();                      // orders remote atomics + s_pred stores

    // ---- fused gather by rank 0: pure-SMEM reads ----
    if (rank == 0) {
        const int s = s_best[tid];
        out[b * NGT + tid] = (s < MPRED) ? s_pred[s] : g;
    }
}

extern "C" void kernel_launch(void* const* d_in, const int* in_sizes, int n_in,
                              void* d_out, int out_size) {
    const float2* gt   = (const float2*)d_in[0];   // gt_locations   [64,1024,2] f32
    const float2* pred = (const float2*)d_in[1];   // pred_locations [64,2048,2] f32
    float2* out = (float2*)d_out;                  // [64,1024,2] f32

    lacss_match_kernel<<<BATCH * 2, 1024>>>(gt, pred, out);
}

// round 11
// speedup vs baseline: 1.2000x; 1.0781x over previous
#include <cuda_runtime.h>
#include <cooperative_groups.h>

namespace cg = cooperative_groups;

#define BATCH   64
#define NGT     1024
#define MPRED   2048
#define THRESH2 256.0f    // 16.0^2
#define GDIM    32        // 32x32 grid of 16px cells (512 / 16)
#define NCELL   (GDIM * GDIM)

// Cluster of 2 CTAs (1024 threads) per batch; grid = 128. Each CTA bins the
// batch's 1024 gts into a 32x32 cell CSR in its own smem, then scans 1024
// preds (rank r -> preds [r*1024, ...)) against the 3x3 cell neighborhood —
// exactly equivalent to the full argmin (matches only matter under the 16px
// threshold, and any gt within 16px of a pred lies in the 3x3 neighborhood
// of the pred's cell). Both ranks atomicMin (gt -> min pred index) into
// RANK 0's s_best (DSMEM atomic for rank 1); cluster.sync(); rank 0 gathers
// from an smem-staged pred slab.
//
// R11: the scan's (d2, gi) lexicographic argmin is ONE u64 min over
// key = (d2_bits << 32) | gi  — valid because d2 >= 0 so IEEE bits order as
// unsigned ints. Init key = bits(256.0f)<<32 folds the threshold: any
// d2 < 256 beats it for every gi; d2 >= 256 never does (strict <, matching
// the reference). min gi within min d2 = jnp.argmin first-index rule,
// order-invariant. Replaces FSETP/FSETP/ISETP/logic/SEL/SEL/FSEL with
// mov.b64 + u64 min in the hottest loop.
//
// d2 uses __fadd_rn/__fmul_rn (no FMA) -> bit-identical to the reference.
__global__ __launch_bounds__(1024, 1) __cluster_dims__(2, 1, 1)
void lacss_match_kernel(
    const float2* __restrict__ gt,    // [BATCH, NGT]
    const float2* __restrict__ pred,  // [BATCH, MPRED]
    float2* __restrict__ out)         // [BATCH, NGT]
{
    __shared__ int    s_cnt[NCELL];      // counts, then scatter cursor
    __shared__ int    s_off[NCELL + 1];  // exclusive CSR offsets
    __shared__ float4 s_pt[NGT];         // {gx, gy, idx-as-float, pad} binned
    __shared__ int    s_best[NGT];       // min matched pred j per gt (rank0 authoritative)
    __shared__ float2 s_pred[MPRED];     // full pred slab (rank0 authoritative)
    __shared__ int    s_wsum[32];

    cg::cluster_group cluster = cg::this_cluster();
    const unsigned rank = cluster.block_rank();

    const int b    = blockIdx.x >> 1;
    const int tid  = threadIdx.x;
    const int lane = tid & 31;
    const int wid  = tid >> 5;

    // ---- prefetch both inputs (MLP=2, DRAM latency behind binning) ----
    const int j = (int)rank * 1024 + tid;          // this thread's pred
    const float2 p = pred[b * MPRED + j];
    const float2 g = gt[b * NGT + tid];

    s_cnt[tid]  = 0;
    s_best[tid] = MPRED;                 // sentinel: unmatched
    __syncthreads();

    // ---- stage pred slab into rank0's smem (overlapped with binning;
    //      visibility at the tail via cluster.sync) ----
    {
        float2* dst = (rank == 0) ? s_pred
                                  : cluster.map_shared_rank(s_pred, 0);
        dst[j] = p;                      // disjoint ranges per rank
    }

    // ---- count (cell = y/16 * 32 + x/16; *2^-4 exact) ----
    const int gcell = (int)(g.y * 0.0625f) * GDIM + (int)(g.x * 0.0625f);
    atomicAdd(&s_cnt[gcell], 1);
    __syncthreads();

    // ---- exclusive prefix sum of s_cnt -> s_off ----
    int v   = s_cnt[tid];
    int inc = v;
    #pragma unroll
    for (int d = 1; d < 32; d <<= 1) {
        int n = __shfl_up_sync(0xFFFFFFFFu, inc, d);
        if (lane >= d) inc += n;
    }
    if (lane == 31) s_wsum[wid] = inc;
    __syncthreads();
    if (wid == 0) {
        int w  = s_wsum[lane];
        int wi = w;
        #pragma unroll
        for (int d = 1; d < 32; d <<= 1) {
            int n = __shfl_up_sync(0xFFFFFFFFu, wi, d);
            if (lane >= d) wi += n;
        }
        s_wsum[lane] = wi - w;           // exclusive offset of warp `lane`
    }
    __syncthreads();
    const int excl = (inc - v) + s_wsum[wid];
    s_off[tid] = excl;
    if (tid == 0) s_off[NCELL] = NGT;
    s_cnt[tid] = excl;                   // cursor = copy of offsets
    __syncthreads();

    // ---- scatter gts into binned order, original idx packed into .z ----
    {
        int pos = atomicAdd(&s_cnt[gcell], 1);
        s_pt[pos] = make_float4(g.x, g.y, __int_as_float(tid), 0.f);
    }
    __syncthreads();

    // ---- pred phase: one pred per thread, 3x3 neighborhood (3 runs),
    //      selection = single u64 min over (d2_bits, gi) ----
    {
        const int pcx = (int)(p.x * 0.0625f);
        const int pcy = (int)(p.y * 0.0625f);
        const int x0 = max(pcx - 1, 0), x1 = min(pcx + 1, GDIM - 1);
        const int y0 = max(pcy - 1, 0), y1 = min(pcy + 1, GDIM - 1);

        const unsigned long long K0 =
            ((unsigned long long)__float_as_uint(THRESH2)) << 32;
        unsigned long long best = K0;

        for (int cy = y0; cy <= y1; cy++) {
            const int ks = s_off[cy * GDIM + x0];
            const int ke = s_off[cy * GDIM + x1 + 1];   // cells contiguous in x
            for (int k = ks; k < ke; k++) {
                float4 q = s_pt[k];                     // one LDS.128
                float dx = __fadd_rn(p.x, -q.x);
                float dy = __fadd_rn(p.y, -q.y);
                float d2 = __fadd_rn(__fmul_rn(dx, dx), __fmul_rn(dy, dy));
                unsigned int bits = __float_as_uint(d2);
                unsigned int gi   = (unsigned int)__float_as_int(q.z);
                unsigned long long key;
                asm("mov.b64 %0, {%1, %2};" : "=l"(key) : "r"(gi), "r"(bits));
                best = (key < best) ? key : best;
            }
        }

        if (best < K0) {
            int bi = (int)(unsigned int)best;           // low word = gt index
            int* dst = (rank == 0) ? s_best
                                   : cluster.map_shared_rank(s_best, 0);
            atomicMin(&dst[bi], j);
        }
    }

    cluster.sync();                      // orders remote atomics + s_pred stores

    // ---- fused gather by rank 0: pure-SMEM reads ----
    if (rank == 0) {
        const int s = s_best[tid];
        out[b * NGT + tid] = (s < MPRED) ? s_pred[s] : g;
    }
}

extern "C" void kernel_launch(void* const* d_in, const int* in_sizes, int n_in,
                              void* d_out, int out_size) {
    const float2* gt   = (const float2*)d_in[0];   // gt_locations   [64,1024,2] f32
    const float2* pred = (const float2*)d_in[1];   // pred_locations [64,2048,2] f32
    float2* out = (float2*)d_out;                  // [64,1024,2] f32

    lacss_match_kernel<<<BATCH * 2, 1024>>>(gt, pred, out);
}